// round 13
// baseline (speedup 1.0000x reference)
#include <cuda_runtime.h>
#include <math_constants.h>

#define N_NODES 20000
#define N_EDGES 640000
#define FIN     128
#define FQK     128
#define FV      128
#define FTOT    384
#define NHEAD   8
#define FH      16

// ---------------- scratch (device globals; no runtime allocation) ----------
__device__ float g_qkv[N_NODES * FTOT];   // [n][0:128)=q*0.25, [128:256)=k, [256:384)=v
__device__ float g_maxw[NHEAD];           // global per-head max
__device__ int   g_dst [N_EDGES];
__device__ int   g_off [N_NODES + 1];     // CSR row offsets over sorted src
// per-node online-softmax state (pass 1 -> pass 2)
__device__ float g_Sv[N_NODES * 128];     // sum of exp(a-m)*v   (per lane slot)
__device__ float g_Vs[N_NODES * 128];     // sum of v            (per lane slot)
__device__ float g_S1[N_NODES * NHEAD];   // sum of exp(a-m)     (per head)
__device__ float g_m [N_NODES * NHEAD];   // node-local max      (per head)

// ---------------- helpers --------------------------------------------------
__device__ __forceinline__ void atomicMaxF(float* addr, float val) {
    int* ai = (int*)addr;
    int old = *ai;
    while (__int_as_float(old) < val) {
        int assumed = old;
        old = atomicCAS(ai, assumed, __float_as_int(val));
        if (old == assumed) break;
    }
}

__device__ __forceinline__ unsigned long long packdup(float a) {
    unsigned long long r;
    asm("mov.b64 %0, {%1, %1};" : "=l"(r) : "f"(a));
    return r;
}
__device__ __forceinline__ void ffma2(unsigned long long& acc,
                                      unsigned long long a, unsigned long long b) {
    asm("fma.rn.f32x2 %0, %1, %2, %0;" : "+l"(acc) : "l"(a), "l"(b));
}
__device__ __forceinline__ void unpack2(unsigned long long p, float& lo, float& hi) {
    asm("mov.b64 {%0, %1}, %2;" : "=f"(lo), "=f"(hi) : "l"(p));
}

// ---------------- kernel B: detect dtype + dst + CSR offsets + init --------
// Per-block redundant dtype detection: sample int64-interpreted words from the
// middle of the src region (in-bounds under both interpretations). int64 =>
// hi-word 0 and lo-word < N for every sample; int32 => the "hi-word" is a
// sorted src value ~N/4 > 0 -> check fails.
__global__ void convert_kernel(const void* ei, int E, int nnodes) {
    __shared__ int s_ok;
    if (threadIdx.x == 0) s_ok = 1;
    __syncthreads();
    {
        const unsigned int* w = (const unsigned int*)ei;
        int i = E / 4 + (int)(threadIdx.x & 127);
        unsigned int lo = w[2 * i];
        unsigned int hi = w[2 * i + 1];
        if (hi != 0u || lo >= (unsigned int)nnodes) atomicAnd(&s_ok, 0);
    }
    if (blockIdx.x == 0 && threadIdx.x < NHEAD) g_maxw[threadIdx.x] = -CUDART_INF_F;
    __syncthreads();
    const int is64 = s_ok;

    int i = blockIdx.x * blockDim.x + threadIdx.x;
    if (i >= E) return;

    int s, sp;
    if (is64) {
        const long long* p = (const long long*)ei;
        s  = (int)p[i];
        sp = (i == 0) ? -1 : (int)p[i - 1];
        g_dst[i] = (int)p[E + i];
    } else {
        const int* p = (const int*)ei;
        s  = p[i];
        sp = (i == 0) ? -1 : p[i - 1];
        g_dst[i] = p[E + i];
    }
    // CSR offsets: g_off[n] = first edge with src >= n
    for (int n = sp + 1; n <= s; n++) g_off[n] = i;
    if (i == E - 1)
        for (int n = s + 1; n <= nnodes; n++) g_off[n] = E;
}

// ---------------- kernel 1: proj = x @ W^T  (packed f32x2 FMAs) ------------
#define TM 64
#define TN 128
#define TK 32
#define BS_STRIDE (TN + 2)
#define AS_STRIDE (TM + 1)

__global__ __launch_bounds__(256) void gemm_kernel(
    const float* __restrict__ x, const float* __restrict__ W, int nrows)
{
    __shared__ float As[TK][AS_STRIDE];
    __shared__ float Bs[TK][BS_STRIDE];
    const int tid = threadIdx.x;
    const int tx = tid & 15, ty = tid >> 4;
    const int rowBase = blockIdx.x * TM;
    const int colBase = blockIdx.y * TN;

    unsigned long long acc2[4][4];
    #pragma unroll
    for (int i = 0; i < 4; i++)
        #pragma unroll
        for (int j = 0; j < 4; j++) acc2[i][j] = 0ull;

    const int lr = tid >> 5;
    const int lc = tid & 31;

    for (int k0 = 0; k0 < FIN; k0 += TK) {
        #pragma unroll
        for (int i = 0; i < 8; i++) {
            int r = lr + i * 8;
            int gr = rowBase + r;
            As[lc][r] = (gr < nrows) ? x[(size_t)gr * FIN + k0 + lc] : 0.f;
        }
        #pragma unroll
        for (int i = 0; i < 16; i++) {
            int r = lr + i * 8;
            Bs[lc][r] = W[(size_t)(colBase + r) * FIN + k0 + lc];
        }
        __syncthreads();

        #pragma unroll
        for (int kk = 0; kk < TK; kk++) {
            unsigned long long ap[4];
            #pragma unroll
            for (int i = 0; i < 4; i++) ap[i] = packdup(As[kk][ty * 4 + i]);
            unsigned long long bp[4];
            #pragma unroll
            for (int j = 0; j < 4; j++)
                bp[j] = *(const unsigned long long*)&Bs[kk][tx * 2 + j * 32];
            #pragma unroll
            for (int i = 0; i < 4; i++)
                #pragma unroll
                for (int j = 0; j < 4; j++)
                    ffma2(acc2[i][j], ap[i], bp[j]);
        }
        __syncthreads();
    }

    const float scale = (colBase == 0) ? 0.25f : 1.0f;  // q block gets FH^-0.5
    #pragma unroll
    for (int i = 0; i < 4; i++) {
        int gr = rowBase + ty * 4 + i;
        if (gr >= nrows) continue;
        #pragma unroll
        for (int j = 0; j < 4; j++) {
            float v0, v1;
            unpack2(acc2[i][j], v0, v1);
            int gc = colBase + tx * 2 + j * 32;
            g_qkv[(size_t)gr * FTOT + gc]     = v0 * scale;
            g_qkv[(size_t)gr * FTOT + gc + 1] = v1 * scale;
        }
    }
}

// ---------------- kernel 2: fused logits + online softmax accumulation -----
// One warp per node (strided). q row register-resident; per edge gather k AND
// v rows (adjacent in g_qkv). Online rescale keeps S1/Sv relative to the
// node-local running max m. Lane l: head h = l>>2, floats [4l, 4l+4).
__global__ __launch_bounds__(256) void attn_kernel(int nnodes)
{
    const int lane   = threadIdx.x & 31;
    const int warp   = (blockIdx.x * blockDim.x + threadIdx.x) >> 5;
    const int nwarps = (gridDim.x * blockDim.x) >> 5;
    const int h = lane >> 2;

    float runmax = -CUDART_INF_F;

    for (int n = warp; n < nnodes; n += nwarps) {
        int lo = g_off[n], hi = g_off[n + 1];
        if (hi <= lo) continue;

        const float4 qv = *(const float4*)(g_qkv + (size_t)n * FTOT + lane * 4);

        float m  = -CUDART_INF_F;
        float S1 = 0.f;
        float4 Sv = make_float4(0.f, 0.f, 0.f, 0.f);
        float4 Vs = make_float4(0.f, 0.f, 0.f, 0.f);

        int e = lo;
        for (; e + 4 <= hi; e += 4) {
            int d0 = g_dst[e],     d1 = g_dst[e + 1];
            int d2 = g_dst[e + 2], d3 = g_dst[e + 3];
            const float* b0 = g_qkv + (size_t)d0 * FTOT + FQK + lane * 4;
            const float* b1 = g_qkv + (size_t)d1 * FTOT + FQK + lane * 4;
            const float* b2 = g_qkv + (size_t)d2 * FTOT + FQK + lane * 4;
            const float* b3 = g_qkv + (size_t)d3 * FTOT + FQK + lane * 4;
            const float4 k0 = *(const float4*)b0;
            const float4 k1 = *(const float4*)b1;
            const float4 k2 = *(const float4*)b2;
            const float4 k3 = *(const float4*)b3;
            const float4 v0 = *(const float4*)(b0 + FQK);
            const float4 v1 = *(const float4*)(b1 + FQK);
            const float4 v2 = *(const float4*)(b2 + FQK);
            const float4 v3 = *(const float4*)(b3 + FQK);

            float t0 = qv.x * k0.x + qv.y * k0.y + qv.z * k0.z + qv.w * k0.w;
            float t1 = qv.x * k1.x + qv.y * k1.y + qv.z * k1.z + qv.w * k1.w;
            float t2 = qv.x * k2.x + qv.y * k2.y + qv.z * k2.z + qv.w * k2.w;
            float t3 = qv.x * k3.x + qv.y * k3.y + qv.z * k3.z + qv.w * k3.w;
            t0 += __shfl_xor_sync(0xFFFFFFFFu, t0, 1);
            t1 += __shfl_xor_sync(0xFFFFFFFFu, t1, 1);
            t2 += __shfl_xor_sync(0xFFFFFFFFu, t2, 1);
            t3 += __shfl_xor_sync(0xFFFFFFFFu, t3, 1);
            t0 += __shfl_xor_sync(0xFFFFFFFFu, t0, 2);
            t1 += __shfl_xor_sync(0xFFFFFFFFu, t1, 2);
            t2 += __shfl_xor_sync(0xFFFFFFFFu, t2, 2);
            t3 += __shfl_xor_sync(0xFFFFFFFFu, t3, 2);

            float mg   = fmaxf(fmaxf(t0, t1), fmaxf(t2, t3));
            float mnew = fmaxf(m, mg);
            float sc   = __expf(m - mnew);    // 0 on first group (m=-inf)
            float w0 = __expf(t0 - mnew);
            float w1 = __expf(t1 - mnew);
            float w2 = __expf(t2 - mnew);
            float w3 = __expf(t3 - mnew);
            m = mnew;
            S1 = S1 * sc + ((w0 + w1) + (w2 + w3));
            Sv.x = Sv.x * sc + w0 * v0.x + w1 * v1.x + w2 * v2.x + w3 * v3.x;
            Sv.y = Sv.y * sc + w0 * v0.y + w1 * v1.y + w2 * v2.y + w3 * v3.y;
            Sv.z = Sv.z * sc + w0 * v0.z + w1 * v1.z + w2 * v2.z + w3 * v3.z;
            Sv.w = Sv.w * sc + w0 * v0.w + w1 * v1.w + w2 * v2.w + w3 * v3.w;
            Vs.x += (v0.x + v1.x) + (v2.x + v3.x);
            Vs.y += (v0.y + v1.y) + (v2.y + v3.y);
            Vs.z += (v0.z + v1.z) + (v2.z + v3.z);
            Vs.w += (v0.w + v1.w) + (v2.w + v3.w);
        }
        for (; e < hi; e++) {
            int d = g_dst[e];
            const float* bp = g_qkv + (size_t)d * FTOT + FQK + lane * 4;
            const float4 kv = *(const float4*)bp;
            const float4 vv = *(const float4*)(bp + FQK);
            float t = qv.x * kv.x + qv.y * kv.y + qv.z * kv.z + qv.w * kv.w;
            t += __shfl_xor_sync(0xFFFFFFFFu, t, 1);
            t += __shfl_xor_sync(0xFFFFFFFFu, t, 2);
            float mnew = fmaxf(m, t);
            float sc = __expf(m - mnew);
            float w  = __expf(t - mnew);
            m = mnew;
            S1 = S1 * sc + w;
            Sv.x = Sv.x * sc + w * vv.x;
            Sv.y = Sv.y * sc + w * vv.y;
            Sv.z = Sv.z * sc + w * vv.z;
            Sv.w = Sv.w * sc + w * vv.w;
            Vs.x += vv.x; Vs.y += vv.y; Vs.z += vv.z; Vs.w += vv.w;
        }

        // store per-node state (coalesced 512B per warp for Sv/Vs)
        *(float4*)(g_Sv + (size_t)n * 128 + lane * 4) = Sv;
        *(float4*)(g_Vs + (size_t)n * 128 + lane * 4) = Vs;
        if ((lane & 3) == 0) {
            g_S1[n * NHEAD + h] = S1;
            g_m [n * NHEAD + h] = m;
        }
        runmax = fmaxf(runmax, m);
    }

    // hierarchical per-head max: registers -> shared -> global
    __shared__ float smax[NHEAD];
    if (threadIdx.x < NHEAD) smax[threadIdx.x] = -CUDART_INF_F;
    __syncthreads();
    if ((lane & 3) == 0 && runmax > -CUDART_INF_F) atomicMaxF(&smax[h], runmax);
    __syncthreads();
    if (threadIdx.x < NHEAD && smax[threadIdx.x] > -CUDART_INF_F)
        atomicMaxF(&g_maxw[threadIdx.x], smax[threadIdx.x]);
}

// ---------------- kernel 3: per-node finalize (no edge traversal) ----------
// out = (s*Sv + eps*Vs) / (s*S1 + eps*deg),  s = exp(m - mx)
__global__ __launch_bounds__(256) void finalize_kernel(
    float* __restrict__ out, int nnodes)
{
    const int lane = threadIdx.x & 31;
    const int n    = (blockIdx.x * blockDim.x + threadIdx.x) >> 5;
    if (n >= nnodes) return;

    int deg = g_off[n + 1] - g_off[n];
    float4 res = make_float4(0.f, 0.f, 0.f, 0.f);
    if (deg > 0) {
        const int h = lane >> 2;
        float s  = __expf(g_m[n * NHEAD + h] - g_maxw[h]);
        float S1 = g_S1[n * NHEAD + h];
        float4 Sv = *(const float4*)(g_Sv + (size_t)n * 128 + lane * 4);
        float4 Vs = *(const float4*)(g_Vs + (size_t)n * 128 + lane * 4);
        float inv = 1.f / (s * S1 + 1e-8f * (float)deg);
        res.x = (s * Sv.x + 1e-8f * Vs.x) * inv;
        res.y = (s * Sv.y + 1e-8f * Vs.y) * inv;
        res.z = (s * Sv.z + 1e-8f * Vs.z) * inv;
        res.w = (s * Sv.w + 1e-8f * Vs.w) * inv;
    }
    ((float4*)out)[(size_t)n * 32 + lane] = res;   // coalesced 512B store
}

// ---------------- launch ---------------------------------------------------
extern "C" void kernel_launch(void* const* d_in, const int* in_sizes, int n_in,
                              void* d_out, int out_size)
{
    const float* x  = (const float*)d_in[0];          // [N, 128]
    const float* W  = (const float*)d_in[1];          // [384, 128]
    // d_in[2] = batch (unused by reference math)
    const void*  ei = d_in[3];                        // [2, E], int32 or int64
    float* out = (float*)d_out;

    const int nrows = in_sizes[0] / FIN;
    const int E     = in_sizes[3] / 2;

    convert_kernel<<<(E + 255) / 256, 256>>>(ei, E, nrows);

    dim3 ggrid((nrows + TM - 1) / TM, FTOT / TN);
    gemm_kernel<<<ggrid, 256>>>(x, W, nrows);

    attn_kernel<<<1250, 256>>>(nrows);                // 10000 warps, 2 nodes/warp

    finalize_kernel<<<(nrows * 32 + 255) / 256, 256>>>(out, nrows);
}

// round 14
// speedup vs baseline: 1.5241x; 1.5241x over previous
#include <cuda_runtime.h>
#include <math_constants.h>

#define N_NODES 20000
#define N_EDGES 640000
#define FIN     128
#define FQK     128
#define FV      128
#define FTOT    384
#define NHEAD   8
#define FH      16

// ---------------- scratch (device globals; no runtime allocation) ----------
__device__ float g_qkv[N_NODES * FTOT];   // [n][0:128)=q*0.25, [128:256)=k, [256:384)=v
__device__ float g_maxw[NHEAD];           // global per-head max
__device__ int   g_dst [N_EDGES];
__device__ int   g_off [N_NODES + 1];     // CSR row offsets over sorted src
// per-node online-softmax state (pass 1 -> pass 2)
__device__ float g_Sv[N_NODES * 128];     // sum of exp(a-m)*v   (per lane slot)
__device__ float g_Vs[N_NODES * 128];     // sum of v            (per lane slot)
__device__ float g_S1[N_NODES * NHEAD];   // sum of exp(a-m)     (per head)
__device__ float g_m [N_NODES * NHEAD];   // node-local max      (per head)

// ---------------- helpers --------------------------------------------------
__device__ __forceinline__ void atomicMaxF(float* addr, float val) {
    int* ai = (int*)addr;
    int old = *ai;
    while (__int_as_float(old) < val) {
        int assumed = old;
        old = atomicCAS(ai, assumed, __float_as_int(val));
        if (old == assumed) break;
    }
}

__device__ __forceinline__ unsigned long long packdup(float a) {
    unsigned long long r;
    asm("mov.b64 %0, {%1, %1};" : "=l"(r) : "f"(a));
    return r;
}
__device__ __forceinline__ void ffma2(unsigned long long& acc,
                                      unsigned long long a, unsigned long long b) {
    asm("fma.rn.f32x2 %0, %1, %2, %0;" : "+l"(acc) : "l"(a), "l"(b));
}
__device__ __forceinline__ void unpack2(unsigned long long p, float& lo, float& hi) {
    asm("mov.b64 {%0, %1}, %2;" : "=f"(lo), "=f"(hi) : "l"(p));
}

// ---------------- kernel B: detect dtype + dst + CSR offsets + init --------
// Per-block redundant dtype detection: sample int64-interpreted words from the
// middle of the src region (in-bounds under both interpretations). int64 =>
// hi-word 0 and lo-word < N for every sample; int32 => the "hi-word" is a
// sorted src value ~N/4 > 0 -> check fails.
__global__ void convert_kernel(const void* ei, int E, int nnodes) {
    __shared__ int s_ok;
    if (threadIdx.x == 0) s_ok = 1;
    __syncthreads();
    {
        const unsigned int* w = (const unsigned int*)ei;
        int i = E / 4 + (int)(threadIdx.x & 127);
        unsigned int lo = w[2 * i];
        unsigned int hi = w[2 * i + 1];
        if (hi != 0u || lo >= (unsigned int)nnodes) atomicAnd(&s_ok, 0);
    }
    if (blockIdx.x == 0 && threadIdx.x < NHEAD) g_maxw[threadIdx.x] = -CUDART_INF_F;
    __syncthreads();
    const int is64 = s_ok;

    int i = blockIdx.x * blockDim.x + threadIdx.x;
    if (i >= E) return;

    int s, sp;
    if (is64) {
        const long long* p = (const long long*)ei;
        s  = (int)p[i];
        sp = (i == 0) ? -1 : (int)p[i - 1];
        g_dst[i] = (int)p[E + i];
    } else {
        const int* p = (const int*)ei;
        s  = p[i];
        sp = (i == 0) ? -1 : p[i - 1];
        g_dst[i] = p[E + i];
    }
    // CSR offsets: g_off[n] = first edge with src >= n
    for (int n = sp + 1; n <= s; n++) g_off[n] = i;
    if (i == E - 1)
        for (int n = s + 1; n <= nnodes; n++) g_off[n] = E;
}

// ---------------- kernel 1: proj = x @ W^T  (packed f32x2 FMAs) ------------
#define TM 64
#define TN 128
#define TK 32
#define BS_STRIDE (TN + 2)
#define AS_STRIDE (TM + 1)

__global__ __launch_bounds__(256) void gemm_kernel(
    const float* __restrict__ x, const float* __restrict__ W, int nrows)
{
    __shared__ float As[TK][AS_STRIDE];
    __shared__ float Bs[TK][BS_STRIDE];
    const int tid = threadIdx.x;
    const int tx = tid & 15, ty = tid >> 4;
    const int rowBase = blockIdx.x * TM;
    const int colBase = blockIdx.y * TN;

    unsigned long long acc2[4][4];
    #pragma unroll
    for (int i = 0; i < 4; i++)
        #pragma unroll
        for (int j = 0; j < 4; j++) acc2[i][j] = 0ull;

    const int lr = tid >> 5;
    const int lc = tid & 31;

    for (int k0 = 0; k0 < FIN; k0 += TK) {
        #pragma unroll
        for (int i = 0; i < 8; i++) {
            int r = lr + i * 8;
            int gr = rowBase + r;
            As[lc][r] = (gr < nrows) ? x[(size_t)gr * FIN + k0 + lc] : 0.f;
        }
        #pragma unroll
        for (int i = 0; i < 16; i++) {
            int r = lr + i * 8;
            Bs[lc][r] = W[(size_t)(colBase + r) * FIN + k0 + lc];
        }
        __syncthreads();

        #pragma unroll
        for (int kk = 0; kk < TK; kk++) {
            unsigned long long ap[4];
            #pragma unroll
            for (int i = 0; i < 4; i++) ap[i] = packdup(As[kk][ty * 4 + i]);
            unsigned long long bp[4];
            #pragma unroll
            for (int j = 0; j < 4; j++)
                bp[j] = *(const unsigned long long*)&Bs[kk][tx * 2 + j * 32];
            #pragma unroll
            for (int i = 0; i < 4; i++)
                #pragma unroll
                for (int j = 0; j < 4; j++)
                    ffma2(acc2[i][j], ap[i], bp[j]);
        }
        __syncthreads();
    }

    const float scale = (colBase == 0) ? 0.25f : 1.0f;  // q block gets FH^-0.5
    #pragma unroll
    for (int i = 0; i < 4; i++) {
        int gr = rowBase + ty * 4 + i;
        if (gr >= nrows) continue;
        #pragma unroll
        for (int j = 0; j < 4; j++) {
            float v0, v1;
            unpack2(acc2[i][j], v0, v1);
            int gc = colBase + tx * 2 + j * 32;
            g_qkv[(size_t)gr * FTOT + gc]     = v0 * scale;
            g_qkv[(size_t)gr * FTOT + gc + 1] = v1 * scale;
        }
    }
}

// ---------------- kernel 2: fused logits + online softmax (reg-lean) -------
// One warp per node (strided). q row register-resident; per 2 edges gather
// k+v rows (adjacent in g_qkv, 4 independent LDG.128). Online rescale keeps
// S1/Sv relative to node-local running max m. Lane l: head h=l>>2.
// __launch_bounds__(256,5): cap ~51 regs -> >=40 resident warps/SM.
__global__ __launch_bounds__(256, 5) void attn_kernel(int nnodes)
{
    const int lane   = threadIdx.x & 31;
    const int warp   = (blockIdx.x * blockDim.x + threadIdx.x) >> 5;
    const int nwarps = (gridDim.x * blockDim.x) >> 5;
    const int h = lane >> 2;

    float runmax = -CUDART_INF_F;

    for (int n = warp; n < nnodes; n += nwarps) {
        const int lo = g_off[n], hi = g_off[n + 1];
        if (hi <= lo) continue;

        const float4 qv = *(const float4*)(g_qkv + n * FTOT + lane * 4);

        float m  = -CUDART_INF_F;
        float S1 = 0.f;
        float4 Sv = make_float4(0.f, 0.f, 0.f, 0.f);
        float4 Vs = make_float4(0.f, 0.f, 0.f, 0.f);

        int e = lo;
        for (; e + 2 <= hi; e += 2) {
            const int d0 = g_dst[e], d1 = g_dst[e + 1];
            const float* p0 = g_qkv + d0 * FTOT + FQK + lane * 4;
            const float* p1 = g_qkv + d1 * FTOT + FQK + lane * 4;
            const float4 k0 = *(const float4*)p0;
            const float4 k1 = *(const float4*)p1;
            const float4 v0 = *(const float4*)(p0 + FQK);
            const float4 v1 = *(const float4*)(p1 + FQK);

            float t0 = qv.x * k0.x + qv.y * k0.y + qv.z * k0.z + qv.w * k0.w;
            float t1 = qv.x * k1.x + qv.y * k1.y + qv.z * k1.z + qv.w * k1.w;
            t0 += __shfl_xor_sync(0xFFFFFFFFu, t0, 1);
            t1 += __shfl_xor_sync(0xFFFFFFFFu, t1, 1);
            t0 += __shfl_xor_sync(0xFFFFFFFFu, t0, 2);
            t1 += __shfl_xor_sync(0xFFFFFFFFu, t1, 2);

            float mnew = fmaxf(m, fmaxf(t0, t1));
            float sc = __expf(m - mnew);     // 0 on first group (m=-inf)
            float w0 = __expf(t0 - mnew);
            float w1 = __expf(t1 - mnew);
            m = mnew;
            S1 = S1 * sc + (w0 + w1);
            Sv.x = Sv.x * sc + (w0 * v0.x + w1 * v1.x);
            Sv.y = Sv.y * sc + (w0 * v0.y + w1 * v1.y);
            Sv.z = Sv.z * sc + (w0 * v0.z + w1 * v1.z);
            Sv.w = Sv.w * sc + (w0 * v0.w + w1 * v1.w);
            Vs.x += v0.x + v1.x;
            Vs.y += v0.y + v1.y;
            Vs.z += v0.z + v1.z;
            Vs.w += v0.w + v1.w;
        }
        if (e < hi) {
            const int d = g_dst[e];
            const float* p0 = g_qkv + d * FTOT + FQK + lane * 4;
            const float4 kv = *(const float4*)p0;
            const float4 vv = *(const float4*)(p0 + FQK);
            float t = qv.x * kv.x + qv.y * kv.y + qv.z * kv.z + qv.w * kv.w;
            t += __shfl_xor_sync(0xFFFFFFFFu, t, 1);
            t += __shfl_xor_sync(0xFFFFFFFFu, t, 2);
            float mnew = fmaxf(m, t);
            float sc = __expf(m - mnew);
            float w  = __expf(t - mnew);
            m = mnew;
            S1 = S1 * sc + w;
            Sv.x = Sv.x * sc + w * vv.x;
            Sv.y = Sv.y * sc + w * vv.y;
            Sv.z = Sv.z * sc + w * vv.z;
            Sv.w = Sv.w * sc + w * vv.w;
            Vs.x += vv.x; Vs.y += vv.y; Vs.z += vv.z; Vs.w += vv.w;
        }

        // store per-node state (coalesced 512B per warp for Sv/Vs)
        *(float4*)(g_Sv + n * 128 + lane * 4) = Sv;
        *(float4*)(g_Vs + n * 128 + lane * 4) = Vs;
        if ((lane & 3) == 0) {
            g_S1[n * NHEAD + h] = S1;
            g_m [n * NHEAD + h] = m;
        }
        runmax = fmaxf(runmax, m);
    }

    // hierarchical per-head max: registers -> shared -> global
    __shared__ float smax[NHEAD];
    if (threadIdx.x < NHEAD) smax[threadIdx.x] = -CUDART_INF_F;
    __syncthreads();
    if ((lane & 3) == 0 && runmax > -CUDART_INF_F) atomicMaxF(&smax[h], runmax);
    __syncthreads();
    if (threadIdx.x < NHEAD && smax[threadIdx.x] > -CUDART_INF_F)
        atomicMaxF(&g_maxw[threadIdx.x], smax[threadIdx.x]);
}

// ---------------- kernel 3: per-node finalize (no edge traversal) ----------
// out = (s*Sv + eps*Vs) / (s*S1 + eps*deg),  s = exp(m - mx)
__global__ __launch_bounds__(256) void finalize_kernel(
    float* __restrict__ out, int nnodes)
{
    const int lane = threadIdx.x & 31;
    const int n    = (blockIdx.x * blockDim.x + threadIdx.x) >> 5;
    if (n >= nnodes) return;

    int deg = g_off[n + 1] - g_off[n];
    float4 res = make_float4(0.f, 0.f, 0.f, 0.f);
    if (deg > 0) {
        const int h = lane >> 2;
        float s  = __expf(g_m[n * NHEAD + h] - g_maxw[h]);
        float S1 = g_S1[n * NHEAD + h];
        float4 Sv = *(const float4*)(g_Sv + n * 128 + lane * 4);
        float4 Vs = *(const float4*)(g_Vs + n * 128 + lane * 4);
        float inv = 1.f / (s * S1 + 1e-8f * (float)deg);
        res.x = (s * Sv.x + 1e-8f * Vs.x) * inv;
        res.y = (s * Sv.y + 1e-8f * Vs.y) * inv;
        res.z = (s * Sv.z + 1e-8f * Vs.z) * inv;
        res.w = (s * Sv.w + 1e-8f * Vs.w) * inv;
    }
    ((float4*)out)[(size_t)n * 32 + lane] = res;   // coalesced 512B store
}

// ---------------- launch ---------------------------------------------------
extern "C" void kernel_launch(void* const* d_in, const int* in_sizes, int n_in,
                              void* d_out, int out_size)
{
    const float* x  = (const float*)d_in[0];          // [N, 128]
    const float* W  = (const float*)d_in[1];          // [384, 128]
    // d_in[2] = batch (unused by reference math)
    const void*  ei = d_in[3];                        // [2, E], int32 or int64
    float* out = (float*)d_out;

    const int nrows = in_sizes[0] / FIN;
    const int E     = in_sizes[3] / 2;

    convert_kernel<<<(E + 255) / 256, 256>>>(ei, E, nrows);

    dim3 ggrid((nrows + TM - 1) / TM, FTOT / TN);
    gemm_kernel<<<ggrid, 256>>>(x, W, nrows);

    attn_kernel<<<1250, 256>>>(nrows);                // 10000 warps, 2 nodes/warp

    finalize_kernel<<<(nrows * 32 + 255) / 256, 256>>>(out, nrows);
}

// round 15
// speedup vs baseline: 1.5915x; 1.0442x over previous
#include <cuda_runtime.h>
#include <cuda_fp16.h>
#include <math_constants.h>

#define N_NODES 20000
#define N_EDGES 640000
#define FIN     128
#define FQK     128
#define FV      128
#define FTOT    384
#define NHEAD   8
#define FH      16

// ---------------- scratch (device globals; no runtime allocation) ----------
__device__ float  g_q  [N_NODES * 128];   // q * 0.25 (fp32)
__device__ __half g_kvh[N_NODES * 256];   // [0:128)=k halves, [128:256)=v halves
__device__ float  g_maxw[NHEAD];          // global per-head max
__device__ int    g_dst [N_EDGES];
__device__ int    g_off [N_NODES + 1];    // CSR row offsets over sorted src
// per-node online-softmax state (pass 1 -> pass 2)
__device__ float g_Sv[N_NODES * 128];     // sum of exp(a-m)*v   (per lane slot)
__device__ float g_Vs[N_NODES * 128];     // sum of v            (per lane slot)
__device__ float g_S1[N_NODES * NHEAD];   // sum of exp(a-m)     (per head)
__device__ float g_m [N_NODES * NHEAD];   // node-local max      (per head)

// ---------------- helpers --------------------------------------------------
__device__ __forceinline__ void atomicMaxF(float* addr, float val) {
    int* ai = (int*)addr;
    int old = *ai;
    while (__int_as_float(old) < val) {
        int assumed = old;
        old = atomicCAS(ai, assumed, __float_as_int(val));
        if (old == assumed) break;
    }
}

__device__ __forceinline__ unsigned long long packdup(float a) {
    unsigned long long r;
    asm("mov.b64 %0, {%1, %1};" : "=l"(r) : "f"(a));
    return r;
}
__device__ __forceinline__ void ffma2(unsigned long long& acc,
                                      unsigned long long a, unsigned long long b) {
    asm("fma.rn.f32x2 %0, %1, %2, %0;" : "+l"(acc) : "l"(a), "l"(b));
}
__device__ __forceinline__ void unpack2(unsigned long long p, float& lo, float& hi) {
    asm("mov.b64 {%0, %1}, %2;" : "=f"(lo), "=f"(hi) : "l"(p));
}

// 4 halves (uint2) -> float4
__device__ __forceinline__ float4 h4_to_f4(uint2 u) {
    __half2 a = *(__half2*)&u.x;
    __half2 b = *(__half2*)&u.y;
    float2 f0 = __half22float2(a);
    float2 f1 = __half22float2(b);
    return make_float4(f0.x, f0.y, f1.x, f1.y);
}

// ---------------- kernel B: detect dtype + dst + CSR offsets + init --------
// Per-block redundant dtype detection: sample int64-interpreted words from the
// middle of the src region (in-bounds under both interpretations). int64 =>
// hi-word 0 and lo-word < N for every sample; int32 => the "hi-word" is a
// sorted src value ~N/4 > 0 -> check fails.
__global__ void convert_kernel(const void* ei, int E, int nnodes) {
    __shared__ int s_ok;
    if (threadIdx.x == 0) s_ok = 1;
    __syncthreads();
    {
        const unsigned int* w = (const unsigned int*)ei;
        int i = E / 4 + (int)(threadIdx.x & 127);
        unsigned int lo = w[2 * i];
        unsigned int hi = w[2 * i + 1];
        if (hi != 0u || lo >= (unsigned int)nnodes) atomicAnd(&s_ok, 0);
    }
    if (blockIdx.x == 0 && threadIdx.x < NHEAD) g_maxw[threadIdx.x] = -CUDART_INF_F;
    __syncthreads();
    const int is64 = s_ok;

    int i = blockIdx.x * blockDim.x + threadIdx.x;
    if (i >= E) return;

    int s, sp;
    if (is64) {
        const long long* p = (const long long*)ei;
        s  = (int)p[i];
        sp = (i == 0) ? -1 : (int)p[i - 1];
        g_dst[i] = (int)p[E + i];
    } else {
        const int* p = (const int*)ei;
        s  = p[i];
        sp = (i == 0) ? -1 : p[i - 1];
        g_dst[i] = p[E + i];
    }
    // CSR offsets: g_off[n] = first edge with src >= n
    for (int n = sp + 1; n <= s; n++) g_off[n] = i;
    if (i == E - 1)
        for (int n = s + 1; n <= nnodes; n++) g_off[n] = E;
}

// ---------------- kernel 1: proj = x @ W^T  (packed f32x2 FMAs) ------------
// Epilogue: q block (colBase 0) -> fp32 g_q with 0.25 scale; k block (128)
// and v block (256) -> fp16 g_kvh.
#define TM 64
#define TN 128
#define TK 32
#define BS_STRIDE (TN + 2)
#define AS_STRIDE (TM + 1)

__global__ __launch_bounds__(256) void gemm_kernel(
    const float* __restrict__ x, const float* __restrict__ W, int nrows)
{
    __shared__ float As[TK][AS_STRIDE];
    __shared__ float Bs[TK][BS_STRIDE];
    const int tid = threadIdx.x;
    const int tx = tid & 15, ty = tid >> 4;
    const int rowBase = blockIdx.x * TM;
    const int colBase = blockIdx.y * TN;

    unsigned long long acc2[4][4];
    #pragma unroll
    for (int i = 0; i < 4; i++)
        #pragma unroll
        for (int j = 0; j < 4; j++) acc2[i][j] = 0ull;

    const int lr = tid >> 5;
    const int lc = tid & 31;

    for (int k0 = 0; k0 < FIN; k0 += TK) {
        #pragma unroll
        for (int i = 0; i < 8; i++) {
            int r = lr + i * 8;
            int gr = rowBase + r;
            As[lc][r] = (gr < nrows) ? x[(size_t)gr * FIN + k0 + lc] : 0.f;
        }
        #pragma unroll
        for (int i = 0; i < 16; i++) {
            int r = lr + i * 8;
            Bs[lc][r] = W[(size_t)(colBase + r) * FIN + k0 + lc];
        }
        __syncthreads();

        #pragma unroll
        for (int kk = 0; kk < TK; kk++) {
            unsigned long long ap[4];
            #pragma unroll
            for (int i = 0; i < 4; i++) ap[i] = packdup(As[kk][ty * 4 + i]);
            unsigned long long bp[4];
            #pragma unroll
            for (int j = 0; j < 4; j++)
                bp[j] = *(const unsigned long long*)&Bs[kk][tx * 2 + j * 32];
            #pragma unroll
            for (int i = 0; i < 4; i++)
                #pragma unroll
                for (int j = 0; j < 4; j++)
                    ffma2(acc2[i][j], ap[i], bp[j]);
        }
        __syncthreads();
    }

    #pragma unroll
    for (int i = 0; i < 4; i++) {
        int gr = rowBase + ty * 4 + i;
        if (gr >= nrows) continue;
        #pragma unroll
        for (int j = 0; j < 4; j++) {
            float v0, v1;
            unpack2(acc2[i][j], v0, v1);
            int gc = colBase + tx * 2 + j * 32;
            if (colBase == 0) {
                // q block: fp32, scaled by FH^-0.5 = 0.25
                g_q[(size_t)gr * 128 + gc]     = v0 * 0.25f;
                g_q[(size_t)gr * 128 + gc + 1] = v1 * 0.25f;
            } else {
                // k (colBase=128) -> kvh[0:128), v (colBase=256) -> kvh[128:256)
                int o = gc - 128;               // k: [0,128), v: [128,256)
                *(__half2*)(g_kvh + (size_t)gr * 256 + o) = __floats2half2_rn(v0, v1);
            }
        }
    }
}

// ---------------- kernel 2: fused logits + online softmax (fp16 gathers) ---
// One warp per node (strided). q row register-resident (fp32); per 2 edges
// gather k+v half-rows (4 independent 8B loads). Online rescale keeps S1/Sv
// relative to node-local running max m. Lane l: head h=l>>2.
__global__ __launch_bounds__(256, 5) void attn_kernel(int nnodes)
{
    const int lane   = threadIdx.x & 31;
    const int warp   = (blockIdx.x * blockDim.x + threadIdx.x) >> 5;
    const int nwarps = (gridDim.x * blockDim.x) >> 5;
    const int h = lane >> 2;

    float runmax = -CUDART_INF_F;

    for (int n = warp; n < nnodes; n += nwarps) {
        const int lo = g_off[n], hi = g_off[n + 1];
        if (hi <= lo) continue;

        const float4 qv = *(const float4*)(g_q + n * 128 + lane * 4);

        float m  = -CUDART_INF_F;
        float S1 = 0.f;
        float4 Sv = make_float4(0.f, 0.f, 0.f, 0.f);
        float4 Vs = make_float4(0.f, 0.f, 0.f, 0.f);

        int e = lo;
        for (; e + 2 <= hi; e += 2) {
            const int d0 = g_dst[e], d1 = g_dst[e + 1];
            const __half* p0 = g_kvh + d0 * 256 + lane * 4;
            const __half* p1 = g_kvh + d1 * 256 + lane * 4;
            const uint2 ku0 = *(const uint2*)p0;
            const uint2 ku1 = *(const uint2*)p1;
            const uint2 vu0 = *(const uint2*)(p0 + 128);
            const uint2 vu1 = *(const uint2*)(p1 + 128);

            const float4 k0 = h4_to_f4(ku0);
            const float4 k1 = h4_to_f4(ku1);
            float t0 = qv.x * k0.x + qv.y * k0.y + qv.z * k0.z + qv.w * k0.w;
            float t1 = qv.x * k1.x + qv.y * k1.y + qv.z * k1.z + qv.w * k1.w;
            t0 += __shfl_xor_sync(0xFFFFFFFFu, t0, 1);
            t1 += __shfl_xor_sync(0xFFFFFFFFu, t1, 1);
            t0 += __shfl_xor_sync(0xFFFFFFFFu, t0, 2);
            t1 += __shfl_xor_sync(0xFFFFFFFFu, t1, 2);

            float mnew = fmaxf(m, fmaxf(t0, t1));
            float sc = __expf(m - mnew);     // 0 on first group (m=-inf)
            float w0 = __expf(t0 - mnew);
            float w1 = __expf(t1 - mnew);
            m = mnew;
            S1 = S1 * sc + (w0 + w1);

            const float4 v0 = h4_to_f4(vu0);
            const float4 v1 = h4_to_f4(vu1);
            Sv.x = Sv.x * sc + (w0 * v0.x + w1 * v1.x);
            Sv.y = Sv.y * sc + (w0 * v0.y + w1 * v1.y);
            Sv.z = Sv.z * sc + (w0 * v0.z + w1 * v1.z);
            Sv.w = Sv.w * sc + (w0 * v0.w + w1 * v1.w);
            Vs.x += v0.x + v1.x;
            Vs.y += v0.y + v1.y;
            Vs.z += v0.z + v1.z;
            Vs.w += v0.w + v1.w;
        }
        if (e < hi) {
            const int d = g_dst[e];
            const __half* p0 = g_kvh + d * 256 + lane * 4;
            const float4 kv = h4_to_f4(*(const uint2*)p0);
            const float4 vv = h4_to_f4(*(const uint2*)(p0 + 128));
            float t = qv.x * kv.x + qv.y * kv.y + qv.z * kv.z + qv.w * kv.w;
            t += __shfl_xor_sync(0xFFFFFFFFu, t, 1);
            t += __shfl_xor_sync(0xFFFFFFFFu, t, 2);
            float mnew = fmaxf(m, t);
            float sc = __expf(m - mnew);
            float w  = __expf(t - mnew);
            m = mnew;
            S1 = S1 * sc + w;
            Sv.x = Sv.x * sc + w * vv.x;
            Sv.y = Sv.y * sc + w * vv.y;
            Sv.z = Sv.z * sc + w * vv.z;
            Sv.w = Sv.w * sc + w * vv.w;
            Vs.x += vv.x; Vs.y += vv.y; Vs.z += vv.z; Vs.w += vv.w;
        }

        // store per-node state (coalesced 512B per warp for Sv/Vs)
        *(float4*)(g_Sv + n * 128 + lane * 4) = Sv;
        *(float4*)(g_Vs + n * 128 + lane * 4) = Vs;
        if ((lane & 3) == 0) {
            g_S1[n * NHEAD + h] = S1;
            g_m [n * NHEAD + h] = m;
        }
        runmax = fmaxf(runmax, m);
    }

    // hierarchical per-head max: registers -> shared -> global
    __shared__ float smax[NHEAD];
    if (threadIdx.x < NHEAD) smax[threadIdx.x] = -CUDART_INF_F;
    __syncthreads();
    if ((lane & 3) == 0 && runmax > -CUDART_INF_F) atomicMaxF(&smax[h], runmax);
    __syncthreads();
    if (threadIdx.x < NHEAD && smax[threadIdx.x] > -CUDART_INF_F)
        atomicMaxF(&g_maxw[threadIdx.x], smax[threadIdx.x]);
}

// ---------------- kernel 3: per-node finalize (no edge traversal) ----------
// out = (s*Sv + eps*Vs) / (s*S1 + eps*deg),  s = exp(m - mx)
__global__ __launch_bounds__(256) void finalize_kernel(
    float* __restrict__ out, int nnodes)
{
    const int lane = threadIdx.x & 31;
    const int n    = (blockIdx.x * blockDim.x + threadIdx.x) >> 5;
    if (n >= nnodes) return;

    int deg = g_off[n + 1] - g_off[n];
    float4 res = make_float4(0.f, 0.f, 0.f, 0.f);
    if (deg > 0) {
        const int h = lane >> 2;
        float s  = __expf(g_m[n * NHEAD + h] - g_maxw[h]);
        float S1 = g_S1[n * NHEAD + h];
        float4 Sv = *(const float4*)(g_Sv + n * 128 + lane * 4);
        float4 Vs = *(const float4*)(g_Vs + n * 128 + lane * 4);
        float inv = 1.f / (s * S1 + 1e-8f * (float)deg);
        res.x = (s * Sv.x + 1e-8f * Vs.x) * inv;
        res.y = (s * Sv.y + 1e-8f * Vs.y) * inv;
        res.z = (s * Sv.z + 1e-8f * Vs.z) * inv;
        res.w = (s * Sv.w + 1e-8f * Vs.w) * inv;
    }
    ((float4*)out)[(size_t)n * 32 + lane] = res;   // coalesced 512B store
}

// ---------------- launch ---------------------------------------------------
extern "C" void kernel_launch(void* const* d_in, const int* in_sizes, int n_in,
                              void* d_out, int out_size)
{
    const float* x  = (const float*)d_in[0];          // [N, 128]
    const float* W  = (const float*)d_in[1];          // [384, 128]
    // d_in[2] = batch (unused by reference math)
    const void*  ei = d_in[3];                        // [2, E], int32 or int64
    float* out = (float*)d_out;

    const int nrows = in_sizes[0] / FIN;
    const int E     = in_sizes[3] / 2;

    convert_kernel<<<(E + 255) / 256, 256>>>(ei, E, nrows);

    dim3 ggrid((nrows + TM - 1) / TM, FTOT / TN);
    gemm_kernel<<<ggrid, 256>>>(x, W, nrows);

    attn_kernel<<<1250, 256>>>(nrows);                // 10000 warps, 2 nodes/warp

    finalize_kernel<<<(nrows * 32 + 255) / 256, 256>>>(out, nrows);
}

// round 16
// speedup vs baseline: 1.6428x; 1.0322x over previous
#include <cuda_runtime.h>
#include <cuda_fp16.h>
#include <math_constants.h>

#define N_NODES 20000
#define N_EDGES 640000
#define FIN     128
#define FQK     128
#define FV      128
#define FTOT    384
#define NHEAD   8
#define FH      16

// ---------------- scratch (device globals; no runtime allocation) ----------
__device__ float  g_q  [N_NODES * 128];   // q * 0.25 (fp32)
__device__ __half g_kvh[N_NODES * 256];   // [0:128)=k halves, [128:256)=v halves
__device__ float  g_maxw[NHEAD];          // global per-head max
__device__ int    g_dst [N_EDGES];
__device__ int    g_off [N_NODES + 1];    // CSR row offsets over sorted src
// per-node online-softmax state (pass 1 -> pass 2)
__device__ float g_Sv[N_NODES * 128];     // sum of exp(a-m)*v   (per lane slot)
__device__ float g_Vs[N_NODES * 128];     // sum of v            (per lane slot)
__device__ float g_S1[N_NODES * NHEAD];   // sum of exp(a-m)     (per head)
__device__ float g_m [N_NODES * NHEAD];   // node-local max      (per head)

// ---------------- helpers --------------------------------------------------
__device__ __forceinline__ void atomicMaxF(float* addr, float val) {
    int* ai = (int*)addr;
    int old = *ai;
    while (__int_as_float(old) < val) {
        int assumed = old;
        old = atomicCAS(ai, assumed, __float_as_int(val));
        if (old == assumed) break;
    }
}

__device__ __forceinline__ unsigned long long packdup(float a) {
    unsigned long long r;
    asm("mov.b64 %0, {%1, %1};" : "=l"(r) : "f"(a));
    return r;
}
__device__ __forceinline__ void ffma2(unsigned long long& acc,
                                      unsigned long long a, unsigned long long b) {
    asm("fma.rn.f32x2 %0, %1, %2, %0;" : "+l"(acc) : "l"(a), "l"(b));
}
__device__ __forceinline__ void unpack2(unsigned long long p, float& lo, float& hi) {
    asm("mov.b64 {%0, %1}, %2;" : "=f"(lo), "=f"(hi) : "l"(p));
}

// 4 halves (uint2) -> float4
__device__ __forceinline__ float4 h4_to_f4(uint2 u) {
    __half2 a = *(__half2*)&u.x;
    __half2 b = *(__half2*)&u.y;
    float2 f0 = __half22float2(a);
    float2 f1 = __half22float2(b);
    return make_float4(f0.x, f0.y, f1.x, f1.y);
}

__device__ __forceinline__ float dot4(float4 a, float4 b) {
    return a.x * b.x + a.y * b.y + a.z * b.z + a.w * b.w;
}

// ---------------- kernel B: detect dtype + dst + CSR offsets + init --------
// Per-block redundant dtype detection: sample int64-interpreted words from the
// middle of the src region (in-bounds under both interpretations). int64 =>
// hi-word 0 and lo-word < N for every sample; int32 => the "hi-word" is a
// sorted src value ~N/4 > 0 -> check fails.
__global__ void convert_kernel(const void* ei, int E, int nnodes) {
    __shared__ int s_ok;
    if (threadIdx.x == 0) s_ok = 1;
    __syncthreads();
    {
        const unsigned int* w = (const unsigned int*)ei;
        int i = E / 4 + (int)(threadIdx.x & 127);
        unsigned int lo = w[2 * i];
        unsigned int hi = w[2 * i + 1];
        if (hi != 0u || lo >= (unsigned int)nnodes) atomicAnd(&s_ok, 0);
    }
    if (blockIdx.x == 0 && threadIdx.x < NHEAD) g_maxw[threadIdx.x] = -CUDART_INF_F;
    __syncthreads();
    const int is64 = s_ok;

    int i = blockIdx.x * blockDim.x + threadIdx.x;
    if (i >= E) return;

    int s, sp;
    if (is64) {
        const long long* p = (const long long*)ei;
        s  = (int)p[i];
        sp = (i == 0) ? -1 : (int)p[i - 1];
        g_dst[i] = (int)p[E + i];
    } else {
        const int* p = (const int*)ei;
        s  = p[i];
        sp = (i == 0) ? -1 : p[i - 1];
        g_dst[i] = p[E + i];
    }
    // CSR offsets: g_off[n] = first edge with src >= n
    for (int n = sp + 1; n <= s; n++) g_off[n] = i;
    if (i == E - 1)
        for (int n = s + 1; n <= nnodes; n++) g_off[n] = E;
}

// ---------------- kernel 1: proj = x @ W^T  (packed f32x2 FMAs) ------------
// Epilogue: q block (colBase 0) -> fp32 g_q with 0.25 scale; k block (128)
// and v block (256) -> fp16 g_kvh.
#define TM 64
#define TN 128
#define TK 32
#define BS_STRIDE (TN + 2)
#define AS_STRIDE (TM + 1)

__global__ __launch_bounds__(256) void gemm_kernel(
    const float* __restrict__ x, const float* __restrict__ W, int nrows)
{
    __shared__ float As[TK][AS_STRIDE];
    __shared__ float Bs[TK][BS_STRIDE];
    const int tid = threadIdx.x;
    const int tx = tid & 15, ty = tid >> 4;
    const int rowBase = blockIdx.x * TM;
    const int colBase = blockIdx.y * TN;

    unsigned long long acc2[4][4];
    #pragma unroll
    for (int i = 0; i < 4; i++)
        #pragma unroll
        for (int j = 0; j < 4; j++) acc2[i][j] = 0ull;

    const int lr = tid >> 5;
    const int lc = tid & 31;

    for (int k0 = 0; k0 < FIN; k0 += TK) {
        #pragma unroll
        for (int i = 0; i < 8; i++) {
            int r = lr + i * 8;
            int gr = rowBase + r;
            As[lc][r] = (gr < nrows) ? x[(size_t)gr * FIN + k0 + lc] : 0.f;
        }
        #pragma unroll
        for (int i = 0; i < 16; i++) {
            int r = lr + i * 8;
            Bs[lc][r] = W[(size_t)(colBase + r) * FIN + k0 + lc];
        }
        __syncthreads();

        #pragma unroll
        for (int kk = 0; kk < TK; kk++) {
            unsigned long long ap[4];
            #pragma unroll
            for (int i = 0; i < 4; i++) ap[i] = packdup(As[kk][ty * 4 + i]);
            unsigned long long bp[4];
            #pragma unroll
            for (int j = 0; j < 4; j++)
                bp[j] = *(const unsigned long long*)&Bs[kk][tx * 2 + j * 32];
            #pragma unroll
            for (int i = 0; i < 4; i++)
                #pragma unroll
                for (int j = 0; j < 4; j++)
                    ffma2(acc2[i][j], ap[i], bp[j]);
        }
        __syncthreads();
    }

    #pragma unroll
    for (int i = 0; i < 4; i++) {
        int gr = rowBase + ty * 4 + i;
        if (gr >= nrows) continue;
        #pragma unroll
        for (int j = 0; j < 4; j++) {
            float v0, v1;
            unpack2(acc2[i][j], v0, v1);
            int gc = colBase + tx * 2 + j * 32;
            if (colBase == 0) {
                // q block: fp32, scaled by FH^-0.5 = 0.25
                g_q[(size_t)gr * 128 + gc]     = v0 * 0.25f;
                g_q[(size_t)gr * 128 + gc + 1] = v1 * 0.25f;
            } else {
                // k (colBase=128) -> kvh[0:128), v (colBase=256) -> kvh[128:256)
                int o = gc - 128;               // k: [0,128), v: [128,256)
                *(__half2*)(g_kvh + (size_t)gr * 256 + o) = __floats2half2_rn(v0, v1);
            }
        }
    }
}

// ---------------- kernel 2: fused logits + online softmax (4-edge unroll) --
// One warp per node (strided). q row register-resident (fp32); per 4 edges
// gather k+v half-rows (8 independent 8B loads) -> 4 overlapping shuffle/exp
// chains, merged once per group. Lane l: head h=l>>2.
__global__ __launch_bounds__(256, 4) void attn_kernel(int nnodes)
{
    const int lane   = threadIdx.x & 31;
    const int warp   = (blockIdx.x * blockDim.x + threadIdx.x) >> 5;
    const int nwarps = (gridDim.x * blockDim.x) >> 5;
    const int h = lane >> 2;

    float runmax = -CUDART_INF_F;

    for (int n = warp; n < nnodes; n += nwarps) {
        const int lo = g_off[n], hi = g_off[n + 1];
        if (hi <= lo) continue;

        const float4 qv = *(const float4*)(g_q + n * 128 + lane * 4);

        float m  = -CUDART_INF_F;
        float S1 = 0.f;
        float4 Sv = make_float4(0.f, 0.f, 0.f, 0.f);
        float4 Vs = make_float4(0.f, 0.f, 0.f, 0.f);

        int e = lo;
        for (; e + 4 <= hi; e += 4) {
            const int d0 = g_dst[e],     d1 = g_dst[e + 1];
            const int d2 = g_dst[e + 2], d3 = g_dst[e + 3];
            const __half* p0 = g_kvh + d0 * 256 + lane * 4;
            const __half* p1 = g_kvh + d1 * 256 + lane * 4;
            const __half* p2 = g_kvh + d2 * 256 + lane * 4;
            const __half* p3 = g_kvh + d3 * 256 + lane * 4;
            const uint2 ku0 = *(const uint2*)p0;
            const uint2 ku1 = *(const uint2*)p1;
            const uint2 ku2 = *(const uint2*)p2;
            const uint2 ku3 = *(const uint2*)p3;
            const uint2 vu0 = *(const uint2*)(p0 + 128);
            const uint2 vu1 = *(const uint2*)(p1 + 128);
            const uint2 vu2 = *(const uint2*)(p2 + 128);
            const uint2 vu3 = *(const uint2*)(p3 + 128);

            float t0 = dot4(qv, h4_to_f4(ku0));
            float t1 = dot4(qv, h4_to_f4(ku1));
            float t2 = dot4(qv, h4_to_f4(ku2));
            float t3 = dot4(qv, h4_to_f4(ku3));
            t0 += __shfl_xor_sync(0xFFFFFFFFu, t0, 1);
            t1 += __shfl_xor_sync(0xFFFFFFFFu, t1, 1);
            t2 += __shfl_xor_sync(0xFFFFFFFFu, t2, 1);
            t3 += __shfl_xor_sync(0xFFFFFFFFu, t3, 1);
            t0 += __shfl_xor_sync(0xFFFFFFFFu, t0, 2);
            t1 += __shfl_xor_sync(0xFFFFFFFFu, t1, 2);
            t2 += __shfl_xor_sync(0xFFFFFFFFu, t2, 2);
            t3 += __shfl_xor_sync(0xFFFFFFFFu, t3, 2);

            float mg   = fmaxf(fmaxf(t0, t1), fmaxf(t2, t3));
            float mnew = fmaxf(m, mg);
            float sc = __expf(m - mnew);     // 0 on first group (m=-inf)
            float w0 = __expf(t0 - mnew);
            float w1 = __expf(t1 - mnew);
            float w2 = __expf(t2 - mnew);
            float w3 = __expf(t3 - mnew);
            m = mnew;
            S1 = S1 * sc + ((w0 + w1) + (w2 + w3));

            const float4 v0 = h4_to_f4(vu0);
            const float4 v1 = h4_to_f4(vu1);
            const float4 v2 = h4_to_f4(vu2);
            const float4 v3 = h4_to_f4(vu3);
            Sv.x = Sv.x * sc + ((w0 * v0.x + w1 * v1.x) + (w2 * v2.x + w3 * v3.x));
            Sv.y = Sv.y * sc + ((w0 * v0.y + w1 * v1.y) + (w2 * v2.y + w3 * v3.y));
            Sv.z = Sv.z * sc + ((w0 * v0.z + w1 * v1.z) + (w2 * v2.z + w3 * v3.z));
            Sv.w = Sv.w * sc + ((w0 * v0.w + w1 * v1.w) + (w2 * v2.w + w3 * v3.w));
            Vs.x += (v0.x + v1.x) + (v2.x + v3.x);
            Vs.y += (v0.y + v1.y) + (v2.y + v3.y);
            Vs.z += (v0.z + v1.z) + (v2.z + v3.z);
            Vs.w += (v0.w + v1.w) + (v2.w + v3.w);
        }
        for (; e < hi; e++) {
            const int d = g_dst[e];
            const __half* p0 = g_kvh + d * 256 + lane * 4;
            const float4 kv = h4_to_f4(*(const uint2*)p0);
            const float4 vv = h4_to_f4(*(const uint2*)(p0 + 128));
            float t = dot4(qv, kv);
            t += __shfl_xor_sync(0xFFFFFFFFu, t, 1);
            t += __shfl_xor_sync(0xFFFFFFFFu, t, 2);
            float mnew = fmaxf(m, t);
            float sc = __expf(m - mnew);
            float w  = __expf(t - mnew);
            m = mnew;
            S1 = S1 * sc + w;
            Sv.x = Sv.x * sc + w * vv.x;
            Sv.y = Sv.y * sc + w * vv.y;
            Sv.z = Sv.z * sc + w * vv.z;
            Sv.w = Sv.w * sc + w * vv.w;
            Vs.x += vv.x; Vs.y += vv.y; Vs.z += vv.z; Vs.w += vv.w;
        }

        // store per-node state (coalesced 512B per warp for Sv/Vs)
        *(float4*)(g_Sv + n * 128 + lane * 4) = Sv;
        *(float4*)(g_Vs + n * 128 + lane * 4) = Vs;
        if ((lane & 3) == 0) {
            g_S1[n * NHEAD + h] = S1;
            g_m [n * NHEAD + h] = m;
        }
        runmax = fmaxf(runmax, m);
    }

    // hierarchical per-head max: registers -> shared -> global
    __shared__ float smax[NHEAD];
    if (threadIdx.x < NHEAD) smax[threadIdx.x] = -CUDART_INF_F;
    __syncthreads();
    if ((lane & 3) == 0 && runmax > -CUDART_INF_F) atomicMaxF(&smax[h], runmax);
    __syncthreads();
    if (threadIdx.x < NHEAD && smax[threadIdx.x] > -CUDART_INF_F)
        atomicMaxF(&g_maxw[threadIdx.x], smax[threadIdx.x]);
}

// ---------------- kernel 3: per-node finalize (no edge traversal) ----------
// out = (s*Sv + eps*Vs) / (s*S1 + eps*deg),  s = exp(m - mx)
__global__ __launch_bounds__(256) void finalize_kernel(
    float* __restrict__ out, int nnodes)
{
    const int lane = threadIdx.x & 31;
    const int n    = (blockIdx.x * blockDim.x + threadIdx.x) >> 5;
    if (n >= nnodes) return;

    int deg = g_off[n + 1] - g_off[n];
    float4 res = make_float4(0.f, 0.f, 0.f, 0.f);
    if (deg > 0) {
        const int h = lane >> 2;
        float s  = __expf(g_m[n * NHEAD + h] - g_maxw[h]);
        float S1 = g_S1[n * NHEAD + h];
        float4 Sv = *(const float4*)(g_Sv + n * 128 + lane * 4);
        float4 Vs = *(const float4*)(g_Vs + n * 128 + lane * 4);
        float inv = 1.f / (s * S1 + 1e-8f * (float)deg);
        res.x = (s * Sv.x + 1e-8f * Vs.x) * inv;
        res.y = (s * Sv.y + 1e-8f * Vs.y) * inv;
        res.z = (s * Sv.z + 1e-8f * Vs.z) * inv;
        res.w = (s * Sv.w + 1e-8f * Vs.w) * inv;
    }
    ((float4*)out)[(size_t)n * 32 + lane] = res;   // coalesced 512B store
}

// ---------------- launch ---------------------------------------------------
extern "C" void kernel_launch(void* const* d_in, const int* in_sizes, int n_in,
                              void* d_out, int out_size)
{
    const float* x  = (const float*)d_in[0];          // [N, 128]
    const float* W  = (const float*)d_in[1];          // [384, 128]
    // d_in[2] = batch (unused by reference math)
    const void*  ei = d_in[3];                        // [2, E], int32 or int64
    float* out = (float*)d_out;

    const int nrows = in_sizes[0] / FIN;
    const int E     = in_sizes[3] / 2;

    convert_kernel<<<(E + 255) / 256, 256>>>(ei, E, nrows);

    dim3 ggrid((nrows + TM - 1) / TM, FTOT / TN);
    gemm_kernel<<<ggrid, 256>>>(x, W, nrows);

    attn_kernel<<<1250, 256>>>(nrows);                // 10000 warps, 2 nodes/warp

    finalize_kernel<<<(nrows * 32 + 255) / 256, 256>>>(out, nrows);
}